// round 4
// baseline (speedup 1.0000x reference)
#include <cuda_runtime.h>
#include <math.h>
#include <stdint.h>

// Problem dims (fixed by the dataset)
#define BDIM  32768
#define DDIM  256
#define KNEI  32
#define HEADS 8
#define DKH   32
#define FFDIM 1024

// ---------------------------------------------------------------------------
// Scratch (device globals; no allocation allowed in kernel_launch)
// ---------------------------------------------------------------------------
__device__ float g_ln1[(size_t)BDIM * DDIM];               // 32 MB
__device__ float g_q  [(size_t)BDIM * DDIM];               // 32 MB
__device__ float g_wkT[(size_t)HEADS * DKH * DDIM];        // 256 KB
__device__ float g_qk [(size_t)BDIM * HEADS * DDIM];       // 256 MB
__device__ float g_ctx[(size_t)BDIM * HEADS * DDIM];       // 256 MB
__device__ float g_att[(size_t)BDIM * DDIM];               // 32 MB
__device__ float g_x  [(size_t)BDIM * DDIM];               // 32 MB
__device__ float g_h2 [(size_t)BDIM * DDIM];               // 32 MB
__device__ float g_ff [(size_t)BDIM * FFDIM];              // 128 MB

// ---------------------------------------------------------------------------
// LayerNorm: one row per block, 256 threads (D == 256)
// ---------------------------------------------------------------------------
__global__ __launch_bounds__(256) void ln_kernel(
    const float* __restrict__ x, const float* __restrict__ g,
    const float* __restrict__ b, float* __restrict__ out)
{
    int row = blockIdx.x;
    int t = threadIdx.x;
    float v = x[(size_t)row * DDIM + t];
    float s = v, s2 = v * v;
    #pragma unroll
    for (int o = 16; o; o >>= 1) {
        s  += __shfl_xor_sync(0xffffffffu, s,  o);
        s2 += __shfl_xor_sync(0xffffffffu, s2, o);
    }
    __shared__ float red[2][8];
    if ((t & 31) == 0) { red[0][t >> 5] = s; red[1][t >> 5] = s2; }
    __syncthreads();
    float ts = 0.f, ts2 = 0.f;
    #pragma unroll
    for (int i = 0; i < 8; i++) { ts += red[0][i]; ts2 += red[1][i]; }
    float mu  = ts * (1.0f / DDIM);
    float var = ts2 * (1.0f / DDIM) - mu * mu;
    float inv = rsqrtf(var + 1e-5f);
    out[(size_t)row * DDIM + t] = (v - mu) * inv * g[t] + b[t];
}

// ---------------------------------------------------------------------------
// Transpose W_k into per-head [d][c] layout: wkT[h][d][c] = W_k[c][h*32+d]
// ---------------------------------------------------------------------------
__global__ __launch_bounds__(256) void wkT_kernel(const float* __restrict__ wk,
                                                  float* __restrict__ wkT)
{
    int idx = blockIdx.x * 256 + threadIdx.x;   // 65536 total
    int c = idx & 255;
    int d = (idx >> 8) & 31;
    int h = idx >> 13;
    wkT[idx] = wk[c * DDIM + h * DKH + d];
}

// ---------------------------------------------------------------------------
// Generic fp32 SGEMM: C = A[M,K] @ B[K,N] (+bias) (gelu) (+res)
// Batched via blockIdx.z with element strides. All dims divide tiles exactly.
// ---------------------------------------------------------------------------
template<int BM, int BN, int BK, int TM, int TN, bool BIAS, bool RES, bool GELU>
__global__ __launch_bounds__((BM / TM) * (BN / TN)) void gemm_kernel(
    const float* __restrict__ A, const float* __restrict__ Bm,
    float* __restrict__ C, const float* __restrict__ bias,
    const float* __restrict__ Rs,
    int M, int N, int Kd, int lda, int ldb, int ldc, int ldr,
    long bsA, long bsB, long bsC)
{
    constexpr int NT  = (BM / TM) * (BN / TN);
    constexpr int PAD = 4;
    __shared__ float As[BK][BM + PAD];
    __shared__ float Bs[BK][BN];

    int t = threadIdx.x;
    int z = blockIdx.z;
    A  += (size_t)z * bsA;
    Bm += (size_t)z * bsB;
    C  += (size_t)z * bsC;

    int m0 = blockIdx.y * BM, n0 = blockIdx.x * BN;
    int tx = t % (BN / TN), ty = t / (BN / TN);

    float acc[TM][TN];
    #pragma unroll
    for (int i = 0; i < TM; i++)
        #pragma unroll
        for (int j = 0; j < TN; j++) acc[i][j] = 0.f;

    constexpr int AF4 = BM * BK / 4 / NT;
    constexpr int BF4 = BK * BN / 4 / NT;

    for (int kt = 0; kt < Kd; kt += BK) {
        #pragma unroll
        for (int i = 0; i < AF4; i++) {
            int f = t + i * NT;
            int k4 = f % (BK / 4), m = f / (BK / 4);
            float4 v = *(const float4*)(A + (size_t)(m0 + m) * lda + kt + k4 * 4);
            As[k4 * 4 + 0][m] = v.x;
            As[k4 * 4 + 1][m] = v.y;
            As[k4 * 4 + 2][m] = v.z;
            As[k4 * 4 + 3][m] = v.w;
        }
        #pragma unroll
        for (int i = 0; i < BF4; i++) {
            int f = t + i * NT;
            int n4 = f % (BN / 4), k = f / (BN / 4);
            *(float4*)&Bs[k][n4 * 4] =
                *(const float4*)(Bm + (size_t)(kt + k) * ldb + n0 + n4 * 4);
        }
        __syncthreads();
        #pragma unroll
        for (int kk = 0; kk < BK; kk++) {
            float a[TM], bb[TN];
            #pragma unroll
            for (int i = 0; i < TM; i++) a[i] = As[kk][ty * TM + i];
            #pragma unroll
            for (int j = 0; j < TN; j++) bb[j] = Bs[kk][tx * TN + j];
            #pragma unroll
            for (int i = 0; i < TM; i++)
                #pragma unroll
                for (int j = 0; j < TN; j++)
                    acc[i][j] = fmaf(a[i], bb[j], acc[i][j]);
        }
        __syncthreads();
    }

    #pragma unroll
    for (int i = 0; i < TM; i++) {
        int m = m0 + ty * TM + i;
        #pragma unroll
        for (int j = 0; j < TN; j++) {
            int n = n0 + tx * TN + j;
            float v = acc[i][j];
            if (BIAS) v += bias[n];
            if (GELU) v = 0.5f * v * (1.0f + erff(v * 0.70710678118654752f));
            if (RES)  v += Rs[(size_t)m * ldr + n];
            C[(size_t)m * ldc + n] = v;
        }
    }
}

// ---------------------------------------------------------------------------
// Fused attention core: one row b per block, 256 threads.
//   scores[h,k] = Xn[k,:]·Qk[h,:] / sqrt(32); softmax over k;
//   ctx[h,c]    = sum_k attn[h,k] * Xn[k,c]
// Xn is held in smem as float4s with XOR swizzle phys = (k<<6) | (c4 ^ k)
// -> conflict-free for the load (lane=c4), scores (lane=k), ctx (lane=c) phases.
// ---------------------------------------------------------------------------
__global__ __launch_bounds__(256) void attn_kernel(
    const float* __restrict__ xnei, const float* __restrict__ qk,
    float* __restrict__ ctx)
{
    int b = blockIdx.x;
    int t = threadIdx.x;
    int lane = t & 31, w = t >> 5;

    __shared__ float4 xns[KNEI * 64];          // 32 KB, swizzled
    __shared__ float4 qks4[HEADS * 64];        // 8 KB; reused as `part` later
    __shared__ float  attn_s[HEADS * KNEI];    // 1 KB
    float* part = (float*)qks4;                // [wp][h][k] = [8][8][32]

    const float4* xg = (const float4*)(xnei + (size_t)b * KNEI * DDIM);
    #pragma unroll
    for (int i = 0; i < 8; i++) {
        int f = t + i * 256;                   // 2048 float4s
        int k = f >> 6, c4 = f & 63;
        xns[(k << 6) | (c4 ^ k)] = xg[f];
    }
    const float4* qg = (const float4*)(qk + (size_t)b * HEADS * DDIM);
    #pragma unroll
    for (int i = 0; i < 2; i++) qks4[t + i * 256] = qg[t + i * 256];
    __syncthreads();

    // scores: warp w owns c4-chunk [8w, 8w+8), lane = neighbor k
    float p[HEADS];
    #pragma unroll
    for (int h = 0; h < HEADS; h++) p[h] = 0.f;
    #pragma unroll
    for (int j = 0; j < 8; j++) {
        int c4 = w * 8 + j;
        float4 v = xns[(lane << 6) | (c4 ^ lane)];
        #pragma unroll
        for (int h = 0; h < HEADS; h++) {
            float4 q4 = qks4[h * 64 + c4];
            p[h] += v.x * q4.x + v.y * q4.y + v.z * q4.z + v.w * q4.w;
        }
    }
    __syncthreads();                           // all qks reads done before alias write
    #pragma unroll
    for (int h = 0; h < HEADS; h++) part[w * 256 + h * 32 + lane] = p[h];
    __syncthreads();

    // softmax: warp w handles head h = w, lane = k
    float s = 0.f;
    #pragma unroll
    for (int wp = 0; wp < 8; wp++) s += part[wp * 256 + w * 32 + lane];
    s *= 0.17677669529663687f;                 // 1/sqrt(32)
    float m = s;
    #pragma unroll
    for (int o = 16; o; o >>= 1) m = fmaxf(m, __shfl_xor_sync(0xffffffffu, m, o));
    float e = __expf(s - m);
    float sum = e;
    #pragma unroll
    for (int o = 16; o; o >>= 1) sum += __shfl_xor_sync(0xffffffffu, sum, o);
    attn_s[w * 32 + lane] = e / sum;
    __syncthreads();

    // ctx: thread owns column c = t, accumulates all 8 heads in registers
    int c = t, c4 = c >> 2, ci = c & 3;
    float cr[HEADS];
    #pragma unroll
    for (int h = 0; h < HEADS; h++) cr[h] = 0.f;
    const float* xnf = (const float*)xns;
    #pragma unroll
    for (int k = 0; k < KNEI; k++) {
        float xv = xnf[(((k << 6) | (c4 ^ k)) << 2) + ci];
        #pragma unroll
        for (int h = 0; h < HEADS; h++) cr[h] += attn_s[h * 32 + k] * xv;
    }
    float* cg = ctx + (size_t)b * HEADS * DDIM;
    #pragma unroll
    for (int h = 0; h < HEADS; h++) cg[h * 256 + c] = cr[h];
}

// ---------------------------------------------------------------------------
// Host: launch pipeline (graph-capturable: kernel launches only)
// ---------------------------------------------------------------------------
template<bool BIAS, bool RES, bool GELU>
static void launch_gemmA(const float* A, const float* B, float* C,
                         const float* bias, const float* res,
                         int M, int N, int Kd, int lda, int ldb, int ldc, int ldr,
                         long bsA, long bsB, long bsC, int batch)
{
    dim3 grid(N / 128, M / 128, batch);
    gemm_kernel<128, 128, 16, 8, 8, BIAS, RES, GELU><<<grid, 256>>>(
        A, B, C, bias, res, M, N, Kd, lda, ldb, ldc, ldr, bsA, bsB, bsC);
}

extern "C" void kernel_launch(void* const* d_in, const int* in_sizes, int n_in,
                              void* d_out, int out_size)
{
    const float* x_anc = (const float*)d_in[0];
    const float* x_nei = (const float*)d_in[1];
    const float* W_q   = (const float*)d_in[2];
    const float* W_k   = (const float*)d_in[3];
    const float* W_v   = (const float*)d_in[4];
    const float* W_o   = (const float*)d_in[5];
    const float* ln1_g = (const float*)d_in[6];
    const float* ln1_b = (const float*)d_in[7];
    const float* ln2_g = (const float*)d_in[8];
    const float* ln2_b = (const float*)d_in[9];
    const float* ff1_w = (const float*)d_in[10];
    const float* ff1_b = (const float*)d_in[11];
    const float* ff2_w = (const float*)d_in[12];
    const float* ff2_b = (const float*)d_in[13];
    float* out = (float*)d_out;

    float *ln1, *q, *wkT, *qk, *ctx, *att, *x, *h2, *ff;
    cudaGetSymbolAddress((void**)&ln1, g_ln1);
    cudaGetSymbolAddress((void**)&q,   g_q);
    cudaGetSymbolAddress((void**)&wkT, g_wkT);
    cudaGetSymbolAddress((void**)&qk,  g_qk);
    cudaGetSymbolAddress((void**)&ctx, g_ctx);
    cudaGetSymbolAddress((void**)&att, g_att);
    cudaGetSymbolAddress((void**)&x,   g_x);
    cudaGetSymbolAddress((void**)&h2,  g_h2);
    cudaGetSymbolAddress((void**)&ff,  g_ff);

    // 1. ln1 = LN(x_anc)
    ln_kernel<<<BDIM, 256>>>(x_anc, ln1_g, ln1_b, ln1);

    // 2. wkT[h][d][c] = W_k[c][h*32+d]
    wkT_kernel<<<HEADS * DKH * DDIM / 256, 256>>>(W_k, wkT);

    // 3. Q = ln1 @ W_q                       [B,256]x[256,256]
    launch_gemmA<false, false, false>(ln1, W_q, q, nullptr, nullptr,
        BDIM, DDIM, DDIM, DDIM, DDIM, DDIM, 0, 0, 0, 0, 1);

    // 4. Qk[b,h,:] = Q[b,h-slice] @ wkT_h    batched [B,32]x[32,256] per head
    launch_gemmA<false, false, false>(q, wkT, qk, nullptr, nullptr,
        BDIM, DDIM, DKH, DDIM, DDIM, HEADS * DDIM, 0,
        /*bsA=*/DKH, /*bsB=*/(long)DKH * DDIM, /*bsC=*/DDIM, HEADS);

    // 5. attention core: scores -> softmax -> ctx   (streams x_nei once)
    attn_kernel<<<BDIM, 256>>>(x_nei, qk, ctx);

    // 6. att[b,h-slice] = ctx[b,h,:] @ W_v[:,h-slice]   batched [B,256]x[256,32]
    {
        dim3 grid(1, BDIM / 128, HEADS);
        gemm_kernel<128, 32, 32, 8, 2, false, false, false><<<grid, 256>>>(
            ctx, W_v, att, nullptr, nullptr,
            BDIM, DKH, DDIM, HEADS * DDIM, DDIM, DDIM, 0,
            /*bsA=*/DDIM, /*bsB=*/DKH, /*bsC=*/DKH);
    }

    // 7. x = x_anc + att @ W_o
    launch_gemmA<false, true, false>(att, W_o, x, nullptr, x_anc,
        BDIM, DDIM, DDIM, DDIM, DDIM, DDIM, DDIM, 0, 0, 0, 1);

    // 8. h2 = LN(x)
    ln_kernel<<<BDIM, 256>>>(x, ln2_g, ln2_b, h2);

    // 9. ff = gelu(h2 @ ff1_w + ff1_b)       [B,256]x[256,1024]
    launch_gemmA<true, false, true>(h2, ff1_w, ff, ff1_b, nullptr,
        BDIM, FFDIM, DDIM, DDIM, FFDIM, FFDIM, 0, 0, 0, 0, 1);

    // 10. out = x + ff @ ff2_w + ff2_b       [B,1024]x[1024,256]
    launch_gemmA<true, true, false>(ff, ff2_w, out, ff2_b, x,
        BDIM, DDIM, FFDIM, FFDIM, DDIM, DDIM, DDIM, 0, 0, 0, 1);
}